// round 7
// baseline (speedup 1.0000x reference)
#include <cuda_runtime.h>
#include <cuda_fp16.h>

#define MAX_NODES 50000
#define MAX_EDGES 800000
#define D 64
#define NBLK 148          // persistent-kernel grid (<= SM count, all co-resident)

// ---------------------------------------------------------------------------
// Scratch (device globals; no allocation allowed)
// ---------------------------------------------------------------------------
__device__ float   g_lin[MAX_NODES * D];      // data @ W_lin^T + b_lin (fp32)
__device__ __half2 g_lin_h[MAX_NODES * (D/2)];// fp16 shadow for gather reads
__device__ float   g_lap[MAX_NODES * D];      // lin - (sum_src lin)/deg
__device__ int     g_deg[MAX_NODES];          // in-degree (zeroed by scan phase for next call)
__device__ int     g_off[MAX_NODES];          // CSR row offsets
__device__ int     g_cur[MAX_NODES];          // fill cursors
__device__ int     g_csum[NBLK];              // per-chunk sums
__device__ int     g_elist[MAX_EDGES];        // src ids in CSR order

// Software grid barrier state (gen is monotonic across calls; cnt returns to 0)
__device__ volatile unsigned g_bar_gen;
__device__ unsigned g_bar_cnt;

__device__ __forceinline__ void grid_bar() {
    __syncthreads();
    if (threadIdx.x == 0) {
        unsigned gen = g_bar_gen;
        __threadfence();                       // publish this block's writes
        unsigned prev = atomicAdd(&g_bar_cnt, 1u);
        if (prev == NBLK - 1) {
            g_bar_cnt = 0;
            __threadfence();
            g_bar_gen = gen + 1;
        } else {
            while (g_bar_gen == gen) { __nanosleep(64); }
        }
    }
    __syncthreads();
}

// ---------------------------------------------------------------------------
// Persistent CSR build: count -> scanA -> scanB' -> fill   (3 grid barriers)
// Requires g_deg == 0 on entry; re-zeros it in scanA for the next call.
// ---------------------------------------------------------------------------
__global__ __launch_bounds__(1024) void build_kernel(
    const int* __restrict__ src, const int* __restrict__ tgt, int n, int E) {
    __shared__ int sh[1024];
    int t = threadIdx.x;
    int bid = blockIdx.x;

    // Phase 1: count in-degrees (atomics are L2-only; no stale-L1 risk)
    for (int e = bid * 1024 + t; e < E; e += NBLK * 1024)
        atomicAdd(&g_deg[__ldg(&tgt[e])], 1);

    grid_bar();

    // Phase 2: per-chunk exclusive scan; also zero g_deg for next invocation
    int chunk = (n + NBLK - 1) / NBLK;              // <= 1024 by construction
    int base = bid * chunk;
    int m = n - base; if (m > chunk) m = chunk; if (m < 0) m = 0;

    int v = 0;
    if (t < m) {
        v = __ldcg(&g_deg[base + t]);
        g_deg[base + t] = 0;                        // restore invariant
    }
    sh[t] = v;
    __syncthreads();
#pragma unroll
    for (int s = 1; s < 1024; s <<= 1) {
        int a = (t >= s) ? sh[t - s] : 0;
        __syncthreads();
        sh[t] += a;
        __syncthreads();
    }
    if (t < m) g_off[base + t] = sh[t] - v;         // local exclusive
    if (t == 1023) g_csum[bid] = sh[1023];

    grid_bar();

    // Phase 3: every block redundantly scans the NBLK chunk sums (no grid=1 stage)
    if (t < 256) sh[t] = (t < NBLK) ? __ldcg(&g_csum[t]) : 0;
    __syncthreads();
#pragma unroll
    for (int s = 1; s < 256; s <<= 1) {
        int a = (t >= s && t < 256) ? sh[t - s] : 0;
        __syncthreads();
        if (t < 256) sh[t] += a;
        __syncthreads();
    }
    int coff = (bid > 0) ? sh[bid - 1] : 0;
    if (t < m) {
        int o = g_off[base + t] + coff;             // own block's write: coherent
        g_off[base + t] = o;
        g_cur[base + t] = o;
    }

    grid_bar();

    // Phase 4: fill edge list via atomic cursors
    for (int e = bid * 1024 + t; e < E; e += NBLK * 1024) {
        int d = __ldg(&tgt[e]);
        int s = __ldg(&src[e]);
        int p = atomicAdd(&g_cur[d], 1);
        g_elist[p] = s;
    }
}

// ---------------------------------------------------------------------------
// GEMM: C = X @ W^T + b.  128x64 block tile, 256 threads, dynamic smem.
// Thread (tx,ty): rows {ty*4..+3, 64+ty*4..+3}, cols {tx*4..+3} -> 32 FMA/k.
// ---------------------------------------------------------------------------
#define SX_STRIDE 132
#define GEMM_SMEM_FLOATS (64 * SX_STRIDE + 64 * 68 + 64)

__device__ __forceinline__ void gemm_core(
    const float* __restrict__ X, const float* __restrict__ W,
    const float* __restrict__ b, int n, int row0,
    float* s_x, float* s_w, float* s_b, float accA[4][4], float accB[4][4]) {
    int t = threadIdx.x;
    for (int i = t; i < 128 * 64; i += 256) {
        int r = i >> 6, k = i & 63;
        int gr = row0 + r;
        s_x[k * SX_STRIDE + r] = (gr < n) ? X[gr * 64 + k] : 0.f;
    }
    for (int i = t; i < 64 * 64; i += 256) {
        int c = i >> 6, k = i & 63;
        s_w[k * 68 + c] = W[c * 64 + k];
    }
    if (t < 64) s_b[t] = b[t];
    __syncthreads();

    int tx = t & 15, ty = t >> 4;
#pragma unroll
    for (int i = 0; i < 4; i++)
#pragma unroll
        for (int j = 0; j < 4; j++) { accA[i][j] = 0.f; accB[i][j] = 0.f; }

#pragma unroll 8
    for (int k = 0; k < 64; k++) {
        float4 xa = *reinterpret_cast<const float4*>(&s_x[k * SX_STRIDE + ty * 4]);
        float4 xb = *reinterpret_cast<const float4*>(&s_x[k * SX_STRIDE + 64 + ty * 4]);
        float4 wv = *reinterpret_cast<const float4*>(&s_w[k * 68 + tx * 4]);
        float xsA[4] = {xa.x, xa.y, xa.z, xa.w};
        float xsB[4] = {xb.x, xb.y, xb.z, xb.w};
        float ws[4]  = {wv.x, wv.y, wv.z, wv.w};
#pragma unroll
        for (int i = 0; i < 4; i++)
#pragma unroll
            for (int j = 0; j < 4; j++) {
                accA[i][j] = fmaf(xsA[i], ws[j], accA[i][j]);
                accB[i][j] = fmaf(xsB[i], ws[j], accB[i][j]);
            }
    }
}

__global__ __launch_bounds__(256) void gemm_lin_kernel(
    const float* __restrict__ X, const float* __restrict__ W,
    const float* __restrict__ b, int n) {
    extern __shared__ float smem[];
    float* s_x = smem;
    float* s_w = smem + 64 * SX_STRIDE;
    float* s_b = s_w + 64 * 68;
    int row0 = blockIdx.x * 128;
    float accA[4][4], accB[4][4];
    gemm_core(X, W, b, n, row0, s_x, s_w, s_b, accA, accB);

    int t = threadIdx.x, tx = t & 15, ty = t >> 4;
#pragma unroll
    for (int half = 0; half < 2; half++) {
#pragma unroll
        for (int i = 0; i < 4; i++) {
            int gr = row0 + half * 64 + ty * 4 + i;
            if (gr < n) {
                float v0 = (half ? accB : accA)[i][0] + s_b[tx * 4 + 0];
                float v1 = (half ? accB : accA)[i][1] + s_b[tx * 4 + 1];
                float v2 = (half ? accB : accA)[i][2] + s_b[tx * 4 + 2];
                float v3 = (half ? accB : accA)[i][3] + s_b[tx * 4 + 3];
                float4* gp = reinterpret_cast<float4*>(g_lin + gr * 64 + tx * 4);
                *gp = make_float4(v0, v1, v2, v3);
                g_lin_h[gr * 32 + tx * 2]     = __floats2half2_rn(v0, v1);
                g_lin_h[gr * 32 + tx * 2 + 1] = __floats2half2_rn(v2, v3);
            }
        }
    }
}

// ---------------------------------------------------------------------------
// Gather: warp per node, fp16 neighbor reads (128B/edge), fp32 accumulate.
// lap = lin_fp32[i] - (sum fp16 lin[src]) / deg   (0 if deg == 0)
// ---------------------------------------------------------------------------
__global__ __launch_bounds__(256) void gather_kernel(int n, int E) {
    int w = (blockIdx.x * 256 + threadIdx.x) >> 5;
    int lane = threadIdx.x & 31;
    if (w >= n) return;

    int beg = g_off[w];
    int end = (w + 1 < n) ? g_off[w + 1] : E;

    float sx = 0.f, sy = 0.f;
    int j = beg;
    for (; j + 4 <= end; j += 4) {
        int s0 = g_elist[j];
        int s1 = g_elist[j + 1];
        int s2 = g_elist[j + 2];
        int s3 = g_elist[j + 3];
        float2 v0 = __half22float2(g_lin_h[s0 * 32 + lane]);
        float2 v1 = __half22float2(g_lin_h[s1 * 32 + lane]);
        float2 v2 = __half22float2(g_lin_h[s2 * 32 + lane]);
        float2 v3 = __half22float2(g_lin_h[s3 * 32 + lane]);
        sx += (v0.x + v1.x) + (v2.x + v3.x);
        sy += (v0.y + v1.y) + (v2.y + v3.y);
    }
    for (; j < end; j++) {
        float2 v = __half22float2(g_lin_h[g_elist[j] * 32 + lane]);
        sx += v.x;
        sy += v.y;
    }

    int deg = end - beg;
    float2 outv;
    if (deg > 0) {
        float inv = 1.f / (float)deg;
        float2 lv = *reinterpret_cast<const float2*>(g_lin + w * 64 + lane * 2);
        outv.x = lv.x - sx * inv;
        outv.y = lv.y - sy * inv;
    } else {
        outv = make_float2(0.f, 0.f);
    }
    reinterpret_cast<float2*>(g_lap + w * 64)[lane] = outv;
}

// ---------------------------------------------------------------------------
// Final: out = relu( (merge @ W_tr^T + b_tr) + lap )
// ---------------------------------------------------------------------------
__global__ __launch_bounds__(256) void final_kernel(
    const float* __restrict__ M, const float* __restrict__ W,
    const float* __restrict__ b, float* __restrict__ out, int n) {
    extern __shared__ float smem[];
    float* s_x = smem;
    float* s_w = smem + 64 * SX_STRIDE;
    float* s_b = s_w + 64 * 68;
    int row0 = blockIdx.x * 128;
    float accA[4][4], accB[4][4];
    gemm_core(M, W, b, n, row0, s_x, s_w, s_b, accA, accB);

    int t = threadIdx.x, tx = t & 15, ty = t >> 4;
#pragma unroll
    for (int half = 0; half < 2; half++) {
#pragma unroll
        for (int i = 0; i < 4; i++) {
            int gr = row0 + half * 64 + ty * 4 + i;
            if (gr < n) {
                const float4 lp = *reinterpret_cast<const float4*>(g_lap + gr * 64 + tx * 4);
                float v0 = (half ? accB : accA)[i][0] + s_b[tx * 4 + 0] + lp.x;
                float v1 = (half ? accB : accA)[i][1] + s_b[tx * 4 + 1] + lp.y;
                float v2 = (half ? accB : accA)[i][2] + s_b[tx * 4 + 2] + lp.z;
                float v3 = (half ? accB : accA)[i][3] + s_b[tx * 4 + 3] + lp.w;
                *reinterpret_cast<float4*>(out + gr * 64 + tx * 4) =
                    make_float4(fmaxf(v0, 0.f), fmaxf(v1, 0.f),
                                fmaxf(v2, 0.f), fmaxf(v3, 0.f));
            }
        }
    }
}

// ---------------------------------------------------------------------------
// Launch: 4 kernels total.
// Inputs: data[N*64], merge[N*64], src_idx[E], tgt_idx[E],
//         W_lin[64*64], b_lin[64], W_tr[64*64], b_tr[64].  Output: float[N*64]
// ---------------------------------------------------------------------------
extern "C" void kernel_launch(void* const* d_in, const int* in_sizes, int n_in,
                              void* d_out, int out_size) {
    const float* data  = (const float*)d_in[0];
    const float* merge = (const float*)d_in[1];
    const int*   src   = (const int*)d_in[2];
    const int*   tgt   = (const int*)d_in[3];
    const float* W_lin = (const float*)d_in[4];
    const float* b_lin = (const float*)d_in[5];
    const float* W_tr  = (const float*)d_in[6];
    const float* b_tr  = (const float*)d_in[7];
    float* out = (float*)d_out;

    int n = in_sizes[0] / D;      // 50000
    int E = in_sizes[2];          // 800000

    size_t gemm_smem = GEMM_SMEM_FLOATS * sizeof(float);   // ~51.5 KB
    cudaFuncSetAttribute(gemm_lin_kernel,
                         cudaFuncAttributeMaxDynamicSharedMemorySize, (int)gemm_smem);
    cudaFuncSetAttribute(final_kernel,
                         cudaFuncAttributeMaxDynamicSharedMemorySize, (int)gemm_smem);

    int gemm_blocks = (n + 127) / 128;

    build_kernel<<<NBLK, 1024>>>(src, tgt, n, E);
    gemm_lin_kernel<<<gemm_blocks, 256, gemm_smem>>>(data, W_lin, b_lin, n);
    gather_kernel<<<(n * 32 + 255) / 256, 256>>>(n, E);
    final_kernel<<<gemm_blocks, 256, gemm_smem>>>(merge, W_tr, b_tr, out, n);
}